// round 1
// baseline (speedup 1.0000x reference)
#include <cuda_runtime.h>
#include <cstdint>
#include <cstddef>

#define T_TOKENS 4096
#define DM 2048
#define DH 1408
#define NE 32
#define NS 2
#define TOPK 6
#define NPASS 34
#define RPAIRS (T_TOKENS * TOPK)          /* 24576 routed pairs */
#define NSLOTS (RPAIRS + NS * T_TOKENS)   /* 32768 total slots  */

#define BM 128
#define BN 128
#define BK 32
#define PAD 8

// ---------------- scratch (static device globals; no allocations) ----------
__device__ float g_H[(size_t)NSLOTS * DH];     // hidden activations, fp32
__device__ float g_gates[T_TOKENS * NE];       // dense gates
__device__ int   g_tok[RPAIRS];                // token id per routed pair
__device__ float g_gate[RPAIRS];               // gate per routed pair
__device__ int   g_cnt[NE];
__device__ int   g_off[NE];
__device__ int   g_cur[NE];
__device__ int   g_passcnt[NPASS];

// ---------------- helpers ---------------------------------------------------
__device__ __forceinline__ uint32_t f2tf32(float x) {
    uint32_t r;
    asm("cvt.rna.tf32.f32 %0, %1;" : "=r"(r) : "f"(x));
    return r;
}

__device__ __forceinline__ void mma_tf32(float* d, const uint32_t* a,
                                         uint32_t b0, uint32_t b1) {
    asm("mma.sync.aligned.m16n8k8.row.col.f32.tf32.tf32.f32 "
        "{%0,%1,%2,%3}, {%4,%5,%6,%7}, {%8,%9}, {%0,%1,%2,%3};"
        : "+f"(d[0]), "+f"(d[1]), "+f"(d[2]), "+f"(d[3])
        : "r"(a[0]), "r"(a[1]), "r"(a[2]), "r"(a[3]), "r"(b0), "r"(b1));
}

// ---------------- small kernels ---------------------------------------------
__global__ void zero_kernel() {
    if (threadIdx.x < NE) g_cnt[threadIdx.x] = 0;
}

__global__ void router_kernel(const float* __restrict__ x,
                              const float* __restrict__ rw,   // [DM][NE]
                              const float* __restrict__ rb) { // [NE]
    int gw   = (blockIdx.x * blockDim.x + threadIdx.x) >> 5;  // token
    int lane = threadIdx.x & 31;                              // expert
    if (gw >= T_TOKENS) return;
    const float* xr = x + (size_t)gw * DM;
    float acc = __ldg(rb + lane);
    for (int k = 0; k < DM; k += 4) {
        float4 xv = *reinterpret_cast<const float4*>(xr + k);
        acc = fmaf(xv.x, __ldg(rw + (k + 0) * NE + lane), acc);
        acc = fmaf(xv.y, __ldg(rw + (k + 1) * NE + lane), acc);
        acc = fmaf(xv.z, __ldg(rw + (k + 2) * NE + lane), acc);
        acc = fmaf(xv.w, __ldg(rw + (k + 3) * NE + lane), acc);
    }
    // softmax across the 32 lanes
    float m = acc;
    for (int o = 16; o; o >>= 1) m = fmaxf(m, __shfl_xor_sync(0xffffffffu, m, o));
    float e = expf(acc - m);
    float s = e;
    for (int o = 16; o; o >>= 1) s += __shfl_xor_sync(0xffffffffu, s, o);
    float p = e / s;
    // iterative top-6 (tie-break: lower index, matching lax.top_k)
    float pv = p, sum6 = 0.0f;
    bool sel = false;
    #pragma unroll
    for (int j = 0; j < TOPK; j++) {
        float v = pv; int idx = lane;
        for (int o = 16; o; o >>= 1) {
            float ov = __shfl_xor_sync(0xffffffffu, v, o);
            int   oi = __shfl_xor_sync(0xffffffffu, idx, o);
            if (ov > v || (ov == v && oi < idx)) { v = ov; idx = oi; }
        }
        sum6 += v;
        if (lane == idx) { pv = -1.0f; sel = true; }
    }
    float gate = sel ? (p / sum6) : 0.0f;
    g_gates[gw * NE + lane] = gate;
    if (sel) atomicAdd(&g_cnt[lane], 1);
}

__global__ void scan_kernel() {
    int lane = threadIdx.x;
    int c = (lane < NE) ? g_cnt[lane] : 0;
    int s = c;
    for (int o = 1; o < 32; o <<= 1) {
        int v = __shfl_up_sync(0xffffffffu, s, o);
        if (lane >= o) s += v;
    }
    if (lane < NE) {
        g_off[lane] = s - c;
        g_cur[lane] = 0;
        g_passcnt[lane] = c;
    }
    if (lane < NS) g_passcnt[NE + lane] = T_TOKENS;
}

__global__ void pairs_kernel() {
    int idx = blockIdx.x * blockDim.x + threadIdx.x;
    if (idx >= T_TOKENS * NE) return;
    int t = idx >> 5, e = idx & 31;
    float gate = g_gates[idx];
    if (gate > 0.0f) {
        int pos = atomicAdd(&g_cur[e], 1);
        g_tok[g_off[e] + pos]  = t;
        g_gate[g_off[e] + pos] = gate;
    }
}

// ---------------- fused expert GEMM ------------------------------------------
// MODE 0: H = relu(gather(X) @ W1 + b1)   K=DM, N=DH, out -> g_H
// MODE 1: out += gate * (H @ W2 + b2)     K=DH, N=DM, atomic scatter
template <int MODE>
__global__ __launch_bounds__(256, 1)
void moe_gemm(const float* __restrict__ Xg,
              const float* __restrict__ RW, const float* __restrict__ RB,
              const float* __restrict__ SW, const float* __restrict__ SB,
              float* __restrict__ OUT) {
    constexpr int K = MODE ? DH : DM;
    constexpr int N = MODE ? DM : DH;

    const int p   = blockIdx.z;
    const int cnt = g_passcnt[p];
    const int m0  = blockIdx.y * BM;
    if (m0 >= cnt) return;                 // uniform early exit
    const int n0  = blockIdx.x * BN;

    const bool routed = (p < NE);
    const int  sidx   = routed ? 0 : (p - NE);
    const int  base   = routed ? g_off[p] : (RPAIRS + sidx * T_TOKENS);
    const float* W    = routed ? (RW + (size_t)p * K * N) : (SW + (size_t)sidx * K * N);
    const float* Bv   = routed ? (RB + (size_t)p * N)     : (SB + (size_t)sidx * N);

    __shared__ uint32_t As[BK][BM + PAD];  // A stored [k][m] (transposed)
    __shared__ uint32_t Bs[BK][BN + PAD];  // B stored [k][n]

    const int tid = threadIdx.x;

    // ---- A loader mapping: thread -> (row in tile, 16-float k-chunk)
    const int ar  = tid & 127;
    const int akc = (tid >> 7) * 16;
    const float* srcA;
    if (MODE == 0) {
        int i = m0 + ar;
        int tok;
        if (routed) {
            int ie = (i < cnt) ? i : (cnt - 1);
            tok = g_tok[base + ie];
        } else {
            tok = i;                       // shared expert: identity gather
        }
        srcA = Xg + (size_t)tok * DM;
    } else {
        srcA = g_H + (size_t)(base + m0 + ar) * DH;   // contiguous slots
    }

    // ---- B loader mapping: thread -> (k row, 16-float n-chunk)
    const int bkr = tid >> 3;
    const int bnc = (tid & 7) * 16;

    // ---- warp / fragment coordinates
    const int wid  = tid >> 5;
    const int lane = tid & 31;
    const int wm = (wid & 3) * 32;         // 4 warps along M
    const int wn = (wid >> 2) * 64;        // 2 warps along N
    const int fg = lane >> 2;              // group id 0..7
    const int ft = lane & 3;               // thread-in-group 0..3

    float acc[2][8][4];
    #pragma unroll
    for (int a = 0; a < 2; a++)
        #pragma unroll
        for (int b = 0; b < 8; b++)
            #pragma unroll
            for (int c = 0; c < 4; c++) acc[a][b][c] = 0.0f;

    float4 pa[4], pb[4];
    {   // prefetch k-tile 0
        const float* a = srcA + akc;
        pa[0] = *reinterpret_cast<const float4*>(a + 0);
        pa[1] = *reinterpret_cast<const float4*>(a + 4);
        pa[2] = *reinterpret_cast<const float4*>(a + 8);
        pa[3] = *reinterpret_cast<const float4*>(a + 12);
        const float* b = W + (size_t)bkr * N + n0 + bnc;
        pb[0] = *reinterpret_cast<const float4*>(b + 0);
        pb[1] = *reinterpret_cast<const float4*>(b + 4);
        pb[2] = *reinterpret_cast<const float4*>(b + 8);
        pb[3] = *reinterpret_cast<const float4*>(b + 12);
    }

    for (int kt = 0; kt < K; kt += BK) {
        __syncthreads();
        // store prefetched tile to smem (convert to tf32, round-to-nearest)
        #pragma unroll
        for (int j = 0; j < 4; j++) {
            float4 v = pa[j];
            As[akc + j * 4 + 0][ar] = f2tf32(v.x);
            As[akc + j * 4 + 1][ar] = f2tf32(v.y);
            As[akc + j * 4 + 2][ar] = f2tf32(v.z);
            As[akc + j * 4 + 3][ar] = f2tf32(v.w);
        }
        #pragma unroll
        for (int j = 0; j < 4; j++) {
            float4 v = pb[j];
            Bs[bkr][bnc + j * 4 + 0] = f2tf32(v.x);
            Bs[bkr][bnc + j * 4 + 1] = f2tf32(v.y);
            Bs[bkr][bnc + j * 4 + 2] = f2tf32(v.z);
            Bs[bkr][bnc + j * 4 + 3] = f2tf32(v.w);
        }
        __syncthreads();

        if (kt + BK < K) {                 // prefetch next tile (overlaps mma)
            const float* a = srcA + kt + BK + akc;
            pa[0] = *reinterpret_cast<const float4*>(a + 0);
            pa[1] = *reinterpret_cast<const float4*>(a + 4);
            pa[2] = *reinterpret_cast<const float4*>(a + 8);
            pa[3] = *reinterpret_cast<const float4*>(a + 12);
            const float* b = W + (size_t)(kt + BK + bkr) * N + n0 + bnc;
            pb[0] = *reinterpret_cast<const float4*>(b + 0);
            pb[1] = *reinterpret_cast<const float4*>(b + 4);
            pb[2] = *reinterpret_cast<const float4*>(b + 8);
            pb[3] = *reinterpret_cast<const float4*>(b + 12);
        }

        // compute: 4 k8-steps, 2 m-frags x 8 n-frags per warp
        #pragma unroll
        for (int kk = 0; kk < 4; kk++) {
            const int kb = kk * 8;
            uint32_t af[2][4];
            #pragma unroll
            for (int mi = 0; mi < 2; mi++) {
                int r = wm + mi * 16 + fg;
                af[mi][0] = As[kb + ft][r];
                af[mi][1] = As[kb + ft][r + 8];
                af[mi][2] = As[kb + ft + 4][r];
                af[mi][3] = As[kb + ft + 4][r + 8];
            }
            #pragma unroll
            for (int nj = 0; nj < 8; nj++) {
                int c = wn + nj * 8 + fg;
                uint32_t b0 = Bs[kb + ft][c];
                uint32_t b1 = Bs[kb + ft + 4][c];
                mma_tf32(acc[0][nj], af[0], b0, b1);
                mma_tf32(acc[1][nj], af[1], b0, b1);
            }
        }
    }

    // ---- epilogue
    #pragma unroll
    for (int mi = 0; mi < 2; mi++) {
        #pragma unroll
        for (int h = 0; h < 2; h++) {      // c0/c1 = row fg, c2/c3 = row fg+8
            int rl = wm + mi * 16 + fg + h * 8;
            int i  = m0 + rl;
            bool valid = (i < cnt);
            int tok = 0; float gate = 0.0f;
            if (MODE == 1 && valid) {
                if (routed) { tok = g_tok[base + i]; gate = g_gate[base + i]; }
                else        { tok = i;               gate = 0.5f; }
            }
            #pragma unroll
            for (int nj = 0; nj < 8; nj++) {
                int col = n0 + wn + nj * 8 + 2 * ft;
                float v0 = acc[mi][nj][h * 2 + 0];
                float v1 = acc[mi][nj][h * 2 + 1];
                if (!valid) continue;
                float bb0 = __ldg(Bv + col);
                float bb1 = __ldg(Bv + col + 1);
                if (MODE == 0) {
                    float s0 = fmaxf(v0 + bb0, 0.0f);
                    float s1 = fmaxf(v1 + bb1, 0.0f);
                    float2* dst = reinterpret_cast<float2*>(
                        g_H + (size_t)(base + i) * DH + col);
                    *dst = make_float2(s0, s1);
                } else {
                    atomicAdd(&OUT[(size_t)tok * DM + col],     gate * (v0 + bb0));
                    atomicAdd(&OUT[(size_t)tok * DM + col + 1], gate * (v1 + bb1));
                }
            }
        }
    }
}

// ---------------- launch -----------------------------------------------------
extern "C" void kernel_launch(void* const* d_in, const int* in_sizes, int n_in,
                              void* d_out, int out_size) {
    const float* x        = (const float*)d_in[0];
    const float* sw1      = (const float*)d_in[1];
    const float* sb1      = (const float*)d_in[2];
    const float* sw2      = (const float*)d_in[3];
    const float* sb2      = (const float*)d_in[4];
    const float* rw1      = (const float*)d_in[5];
    const float* rb1      = (const float*)d_in[6];
    const float* rw2      = (const float*)d_in[7];
    const float* rb2      = (const float*)d_in[8];
    const float* router_w = (const float*)d_in[9];
    const float* router_b = (const float*)d_in[10];
    float* out = (float*)d_out;

    cudaMemsetAsync(out, 0, (size_t)out_size * sizeof(float));
    zero_kernel<<<1, 32>>>();
    router_kernel<<<(T_TOKENS * 32) / 256, 256>>>(x, router_w, router_b);
    scan_kernel<<<1, 32>>>();
    pairs_kernel<<<(T_TOKENS * NE) / 256, 256>>>();

    dim3 g1(DH / BN, T_TOKENS / BM, NPASS);   // (11, 32, 34)
    moe_gemm<0><<<g1, 256>>>(x, rw1, rb1, sw1, sb1, nullptr);

    dim3 g2(DM / BN, T_TOKENS / BM, NPASS);   // (16, 32, 34)
    moe_gemm<1><<<g2, 256>>>(nullptr, rw2, rb2, sw2, sb2, out);
}

// round 2
// speedup vs baseline: 1.0016x; 1.0016x over previous
#include <cuda_runtime.h>
#include <cstdint>
#include <cstddef>

#define T_TOKENS 4096
#define DM 2048
#define DH 1408
#define NE 32
#define NS 2
#define TOPK 6
#define NPASS 34
#define RPAIRS (T_TOKENS * TOPK)          /* 24576 routed pairs */
#define NSLOTS (RPAIRS + NS * T_TOKENS)   /* 32768 total slots  */

#define BM 128
#define BN 128
#define BK 32
#define PAD 8

// ---------------- scratch (static device globals; no allocations) ----------
__device__ float g_H[(size_t)NSLOTS * DH];     // hidden activations, fp32
__device__ float g_gates[T_TOKENS * NE];       // dense gates
__device__ int   g_tok[RPAIRS];                // token id per routed pair
__device__ float g_gate[RPAIRS];               // gate per routed pair
__device__ int   g_cnt[NE];
__device__ int   g_off[NE];
__device__ int   g_cur[NE];
__device__ int   g_passcnt[NPASS];

// ---------------- helpers ---------------------------------------------------
__device__ __forceinline__ uint32_t f2tf32(float x) {
    uint32_t r;
    asm("cvt.rna.tf32.f32 %0, %1;" : "=r"(r) : "f"(x));
    return r;
}

__device__ __forceinline__ void mma_tf32(float* d, const uint32_t* a,
                                         uint32_t b0, uint32_t b1) {
    asm("mma.sync.aligned.m16n8k8.row.col.f32.tf32.tf32.f32 "
        "{%0,%1,%2,%3}, {%4,%5,%6,%7}, {%8,%9}, {%0,%1,%2,%3};"
        : "+f"(d[0]), "+f"(d[1]), "+f"(d[2]), "+f"(d[3])
        : "r"(a[0]), "r"(a[1]), "r"(a[2]), "r"(a[3]), "r"(b0), "r"(b1));
}

// ---------------- small kernels ---------------------------------------------
__global__ void zero_kernel() {
    if (threadIdx.x < NE) g_cnt[threadIdx.x] = 0;
}

__global__ void router_kernel(const float* __restrict__ x,
                              const float* __restrict__ rw,   // [DM][NE]
                              const float* __restrict__ rb) { // [NE]
    int gw   = (blockIdx.x * blockDim.x + threadIdx.x) >> 5;  // token
    int lane = threadIdx.x & 31;                              // expert
    if (gw >= T_TOKENS) return;
    const float* xr = x + (size_t)gw * DM;
    float acc = __ldg(rb + lane);
    for (int k = 0; k < DM; k += 4) {
        float4 xv = *reinterpret_cast<const float4*>(xr + k);
        acc = fmaf(xv.x, __ldg(rw + (k + 0) * NE + lane), acc);
        acc = fmaf(xv.y, __ldg(rw + (k + 1) * NE + lane), acc);
        acc = fmaf(xv.z, __ldg(rw + (k + 2) * NE + lane), acc);
        acc = fmaf(xv.w, __ldg(rw + (k + 3) * NE + lane), acc);
    }
    // softmax across the 32 lanes
    float m = acc;
    for (int o = 16; o; o >>= 1) m = fmaxf(m, __shfl_xor_sync(0xffffffffu, m, o));
    float e = expf(acc - m);
    float s = e;
    for (int o = 16; o; o >>= 1) s += __shfl_xor_sync(0xffffffffu, s, o);
    float p = e / s;
    // iterative top-6 (tie-break: lower index, matching lax.top_k)
    float pv = p, sum6 = 0.0f;
    bool sel = false;
    #pragma unroll
    for (int j = 0; j < TOPK; j++) {
        float v = pv; int idx = lane;
        for (int o = 16; o; o >>= 1) {
            float ov = __shfl_xor_sync(0xffffffffu, v, o);
            int   oi = __shfl_xor_sync(0xffffffffu, idx, o);
            if (ov > v || (ov == v && oi < idx)) { v = ov; idx = oi; }
        }
        sum6 += v;
        if (lane == idx) { pv = -1.0f; sel = true; }
    }
    float gate = sel ? (p / sum6) : 0.0f;
    g_gates[gw * NE + lane] = gate;
    if (sel) atomicAdd(&g_cnt[lane], 1);
}

__global__ void scan_kernel() {
    int lane = threadIdx.x;
    int c = (lane < NE) ? g_cnt[lane] : 0;
    int s = c;
    for (int o = 1; o < 32; o <<= 1) {
        int v = __shfl_up_sync(0xffffffffu, s, o);
        if (lane >= o) s += v;
    }
    if (lane < NE) {
        g_off[lane] = s - c;
        g_cur[lane] = 0;
        g_passcnt[lane] = c;
    }
    if (lane < NS) g_passcnt[NE + lane] = T_TOKENS;
}

__global__ void pairs_kernel() {
    int idx = blockIdx.x * blockDim.x + threadIdx.x;
    if (idx >= T_TOKENS * NE) return;
    int t = idx >> 5, e = idx & 31;
    float gate = g_gates[idx];
    if (gate > 0.0f) {
        int pos = atomicAdd(&g_cur[e], 1);
        g_tok[g_off[e] + pos]  = t;
        g_gate[g_off[e] + pos] = gate;
    }
}

// ---------------- fused expert GEMM ------------------------------------------
// MODE 0: H = relu(gather(X) @ W1 + b1)   K=DM, N=DH, out -> g_H
// MODE 1: out += gate * (H @ W2 + b2)     K=DH, N=DM, atomic scatter
template <int MODE>
__global__ __launch_bounds__(256, 1)
void moe_gemm(const float* __restrict__ Xg,
              const float* __restrict__ RW, const float* __restrict__ RB,
              const float* __restrict__ SW, const float* __restrict__ SB,
              float* __restrict__ OUT) {
    constexpr int K = MODE ? DH : DM;
    constexpr int N = MODE ? DM : DH;

    const int p   = blockIdx.z;
    const int cnt = g_passcnt[p];
    const int m0  = blockIdx.y * BM;
    if (m0 >= cnt) return;                 // uniform early exit
    const int n0  = blockIdx.x * BN;

    const bool routed = (p < NE);
    const int  sidx   = routed ? 0 : (p - NE);
    const int  base   = routed ? g_off[p] : (RPAIRS + sidx * T_TOKENS);
    const float* W    = routed ? (RW + (size_t)p * K * N) : (SW + (size_t)sidx * K * N);
    const float* Bv   = routed ? (RB + (size_t)p * N)     : (SB + (size_t)sidx * N);

    __shared__ uint32_t As[BK][BM + PAD];  // A stored [k][m] (transposed)
    __shared__ uint32_t Bs[BK][BN + PAD];  // B stored [k][n]

    const int tid = threadIdx.x;

    // ---- A loader mapping: thread -> (row in tile, 16-float k-chunk)
    const int ar  = tid & 127;
    const int akc = (tid >> 7) * 16;
    const float* srcA;
    if (MODE == 0) {
        int i = m0 + ar;
        int tok;
        if (routed) {
            int ie = (i < cnt) ? i : (cnt - 1);
            tok = g_tok[base + ie];
        } else {
            tok = i;                       // shared expert: identity gather
        }
        srcA = Xg + (size_t)tok * DM;
    } else {
        srcA = g_H + (size_t)(base + m0 + ar) * DH;   // contiguous slots
    }

    // ---- B loader mapping: thread -> (k row, 16-float n-chunk)
    const int bkr = tid >> 3;
    const int bnc = (tid & 7) * 16;

    // ---- warp / fragment coordinates
    const int wid  = tid >> 5;
    const int lane = tid & 31;
    const int wm = (wid & 3) * 32;         // 4 warps along M
    const int wn = (wid >> 2) * 64;        // 2 warps along N
    const int fg = lane >> 2;              // group id 0..7
    const int ft = lane & 3;               // thread-in-group 0..3

    float acc[2][8][4];
    #pragma unroll
    for (int a = 0; a < 2; a++)
        #pragma unroll
        for (int b = 0; b < 8; b++)
            #pragma unroll
            for (int c = 0; c < 4; c++) acc[a][b][c] = 0.0f;

    float4 pa[4], pb[4];
    {   // prefetch k-tile 0
        const float* a = srcA + akc;
        pa[0] = *reinterpret_cast<const float4*>(a + 0);
        pa[1] = *reinterpret_cast<const float4*>(a + 4);
        pa[2] = *reinterpret_cast<const float4*>(a + 8);
        pa[3] = *reinterpret_cast<const float4*>(a + 12);
        const float* b = W + (size_t)bkr * N + n0 + bnc;
        pb[0] = *reinterpret_cast<const float4*>(b + 0);
        pb[1] = *reinterpret_cast<const float4*>(b + 4);
        pb[2] = *reinterpret_cast<const float4*>(b + 8);
        pb[3] = *reinterpret_cast<const float4*>(b + 12);
    }

    for (int kt = 0; kt < K; kt += BK) {
        __syncthreads();
        // store prefetched tile to smem (convert to tf32, round-to-nearest)
        #pragma unroll
        for (int j = 0; j < 4; j++) {
            float4 v = pa[j];
            As[akc + j * 4 + 0][ar] = f2tf32(v.x);
            As[akc + j * 4 + 1][ar] = f2tf32(v.y);
            As[akc + j * 4 + 2][ar] = f2tf32(v.z);
            As[akc + j * 4 + 3][ar] = f2tf32(v.w);
        }
        #pragma unroll
        for (int j = 0; j < 4; j++) {
            float4 v = pb[j];
            Bs[bkr][bnc + j * 4 + 0] = f2tf32(v.x);
            Bs[bkr][bnc + j * 4 + 1] = f2tf32(v.y);
            Bs[bkr][bnc + j * 4 + 2] = f2tf32(v.z);
            Bs[bkr][bnc + j * 4 + 3] = f2tf32(v.w);
        }
        __syncthreads();

        if (kt + BK < K) {                 // prefetch next tile (overlaps mma)
            const float* a = srcA + kt + BK + akc;
            pa[0] = *reinterpret_cast<const float4*>(a + 0);
            pa[1] = *reinterpret_cast<const float4*>(a + 4);
            pa[2] = *reinterpret_cast<const float4*>(a + 8);
            pa[3] = *reinterpret_cast<const float4*>(a + 12);
            const float* b = W + (size_t)(kt + BK + bkr) * N + n0 + bnc;
            pb[0] = *reinterpret_cast<const float4*>(b + 0);
            pb[1] = *reinterpret_cast<const float4*>(b + 4);
            pb[2] = *reinterpret_cast<const float4*>(b + 8);
            pb[3] = *reinterpret_cast<const float4*>(b + 12);
        }

        // compute: 4 k8-steps, 2 m-frags x 8 n-frags per warp
        #pragma unroll
        for (int kk = 0; kk < 4; kk++) {
            const int kb = kk * 8;
            uint32_t af[2][4];
            #pragma unroll
            for (int mi = 0; mi < 2; mi++) {
                int r = wm + mi * 16 + fg;
                af[mi][0] = As[kb + ft][r];
                af[mi][1] = As[kb + ft][r + 8];
                af[mi][2] = As[kb + ft + 4][r];
                af[mi][3] = As[kb + ft + 4][r + 8];
            }
            #pragma unroll
            for (int nj = 0; nj < 8; nj++) {
                int c = wn + nj * 8 + fg;
                uint32_t b0 = Bs[kb + ft][c];
                uint32_t b1 = Bs[kb + ft + 4][c];
                mma_tf32(acc[0][nj], af[0], b0, b1);
                mma_tf32(acc[1][nj], af[1], b0, b1);
            }
        }
    }

    // ---- epilogue
    #pragma unroll
    for (int mi = 0; mi < 2; mi++) {
        #pragma unroll
        for (int h = 0; h < 2; h++) {      // c0/c1 = row fg, c2/c3 = row fg+8
            int rl = wm + mi * 16 + fg + h * 8;
            int i  = m0 + rl;
            bool valid = (i < cnt);
            int tok = 0; float gate = 0.0f;
            if (MODE == 1 && valid) {
                if (routed) { tok = g_tok[base + i]; gate = g_gate[base + i]; }
                else        { tok = i;               gate = 0.5f; }
            }
            #pragma unroll
            for (int nj = 0; nj < 8; nj++) {
                int col = n0 + wn + nj * 8 + 2 * ft;
                float v0 = acc[mi][nj][h * 2 + 0];
                float v1 = acc[mi][nj][h * 2 + 1];
                if (!valid) continue;
                float bb0 = __ldg(Bv + col);
                float bb1 = __ldg(Bv + col + 1);
                if (MODE == 0) {
                    float s0 = fmaxf(v0 + bb0, 0.0f);
                    float s1 = fmaxf(v1 + bb1, 0.0f);
                    float2* dst = reinterpret_cast<float2*>(
                        g_H + (size_t)(base + i) * DH + col);
                    *dst = make_float2(s0, s1);
                } else {
                    atomicAdd(&OUT[(size_t)tok * DM + col],     gate * (v0 + bb0));
                    atomicAdd(&OUT[(size_t)tok * DM + col + 1], gate * (v1 + bb1));
                }
            }
        }
    }
}

// ---------------- launch -----------------------------------------------------
extern "C" void kernel_launch(void* const* d_in, const int* in_sizes, int n_in,
                              void* d_out, int out_size) {
    const float* x        = (const float*)d_in[0];
    const float* sw1      = (const float*)d_in[1];
    const float* sb1      = (const float*)d_in[2];
    const float* sw2      = (const float*)d_in[3];
    const float* sb2      = (const float*)d_in[4];
    const float* rw1      = (const float*)d_in[5];
    const float* rb1      = (const float*)d_in[6];
    const float* rw2      = (const float*)d_in[7];
    const float* rb2      = (const float*)d_in[8];
    const float* router_w = (const float*)d_in[9];
    const float* router_b = (const float*)d_in[10];
    float* out = (float*)d_out;

    cudaMemsetAsync(out, 0, (size_t)out_size * sizeof(float));
    zero_kernel<<<1, 32>>>();
    router_kernel<<<(T_TOKENS * 32) / 256, 256>>>(x, router_w, router_b);
    scan_kernel<<<1, 32>>>();
    pairs_kernel<<<(T_TOKENS * NE) / 256, 256>>>();

    dim3 g1(DH / BN, T_TOKENS / BM, NPASS);   // (11, 32, 34)
    moe_gemm<0><<<g1, 256>>>(x, rw1, rb1, sw1, sb1, nullptr);

    dim3 g2(DM / BN, T_TOKENS / BM, NPASS);   // (16, 32, 34)
    moe_gemm<1><<<g2, 256>>>(nullptr, rw2, rb2, sw2, sb2, out);
}